// round 6
// baseline (speedup 1.0000x reference)
#include <cuda_runtime.h>

#define BATCH 2
#define SEQ   2048
#define DMODEL 1024
#define NHEAD 16
#define HDIM  64
#define MROWS (BATCH * SEQ)   // 4096

// ---------------------------------------------------------------------------
// Scratch
// ---------------------------------------------------------------------------
__device__ float g_Q[BATCH * NHEAD * SEQ * HDIM];    // [B,H,S,Hd]
__device__ float g_K[BATCH * NHEAD * SEQ * HDIM];
__device__ float g_V[BATCH * NHEAD * SEQ * HDIM];
__device__ float g_CTX[MROWS * DMODEL];              // [B,S,D]

// ---------------------------------------------------------------------------
// helpers
// ---------------------------------------------------------------------------
__device__ __forceinline__ unsigned f2tf(float x) {
    unsigned u;
    asm("cvt.rna.tf32.f32 %0, %1;" : "=r"(u) : "f"(x));
    return u;
}

__device__ __forceinline__ void mma8(float* c, const unsigned* a, unsigned b0, unsigned b1) {
    asm("mma.sync.aligned.m16n8k8.row.col.f32.tf32.tf32.f32 "
        "{%0,%1,%2,%3},{%4,%5,%6,%7},{%8,%9},{%0,%1,%2,%3};"
        : "+f"(c[0]), "+f"(c[1]), "+f"(c[2]), "+f"(c[3])
        : "r"(a[0]), "r"(a[1]), "r"(a[2]), "r"(a[3]), "r"(b0), "r"(b1));
}

__device__ __forceinline__ uint4 ldsm4(unsigned addr) {
    uint4 r;
    asm volatile("ldmatrix.sync.aligned.m8n8.x4.shared.b16 {%0,%1,%2,%3}, [%4];"
        : "=r"(r.x), "=r"(r.y), "=r"(r.z), "=r"(r.w) : "r"(addr));
    return r;
}

__device__ __forceinline__ float ex2_mufu(float t) {
    float y;
    asm("ex2.approx.f32 %0, %1;" : "=f"(y) : "f"(t));
    return y;
}
__device__ __forceinline__ float ex2_poly(float t) {
    const float C = 12582912.0f;  // 1.5 * 2^23
    float r = __fadd_rn(t, C);
    float f = __fsub_rn(t, __fsub_rn(r, C));
    unsigned sb = (((unsigned)__float_as_int(r)) << 23) + 0x3f800000u;
    float p = 0.0096181f;
    p = fmaf(p, f, 0.0554906f);
    p = fmaf(p, f, 0.2401597f);
    p = fmaf(p, f, 0.6931472f);
    p = fmaf(p, f, 1.0f);
    return p * __int_as_float((int)sb);
}

// ---------------------------------------------------------------------------
// tf32 GEMM core, double-buffered: C[M,N] = A[M,K] @ W[N,K]^T + bias[N]
// Block 128x128, BK=16, 256 threads (8 warps 2x4), warp tile 64x32.
// One __syncthreads per K-iter; LDG prefetch overlaps mma.
// ---------------------------------------------------------------------------
template<int MODE>
__device__ __forceinline__ void gemm_body(
    const float* __restrict__ A, const float* __restrict__ W,
    const float* __restrict__ bias, float* __restrict__ C,
    int M, int N, int K, int bx, int by)
{
    __shared__ __align__(16) unsigned As[2][128 * 20];
    __shared__ __align__(16) unsigned Bs[2][128 * 20];

    const int tid = threadIdx.x;
    const int lane = tid & 31, warp = tid >> 5;
    const int gid = lane >> 2, tg = lane & 3;
    const int m0 = by * 128, n0 = bx * 128;
    const int wm = (warp >> 2) * 64, wn = (warp & 3) * 32;

    const int lr = tid >> 2;           // 0..63
    const int lc = (tid & 3) << 2;     // 0,4,8,12
    const float* Ap0 = A + (long)(m0 + lr) * K + lc;
    const float* Ap1 = A + (long)(m0 + lr + 64) * K + lc;
    const float* Wp0 = W + (long)(n0 + lr) * K + lc;
    const float* Wp1 = W + (long)(n0 + lr + 64) * K + lc;

    const unsigned sA = (unsigned)__cvta_generic_to_shared(As);
    const unsigned sB = (unsigned)__cvta_generic_to_shared(Bs);
    const unsigned aAddr0 = sA + (((wm + (lane & 7) + ((lane >> 3) & 1) * 8) * 20
                                   + ((lane >> 4) & 1) * 4) << 2);
    const unsigned bAddr0 = sB + (((wn + (lane >> 4) * 8 + (lane & 7)) * 20
                                   + ((lane >> 3) & 1) * 4) << 2);

    float acc[4][4][4];
#pragma unroll
    for (int mt = 0; mt < 4; mt++)
#pragma unroll
        for (int nt = 0; nt < 4; nt++)
#pragma unroll
            for (int i = 0; i < 4; i++) acc[mt][nt][i] = 0.0f;

    // tile 0 -> buffer 0
    {
        float4 a0 = *(const float4*)Ap0;
        float4 a1 = *(const float4*)Ap1;
        float4 b0 = *(const float4*)Wp0;
        float4 b1 = *(const float4*)Wp1;
        *(uint4*)&As[0][lr * 20 + lc]        = make_uint4(f2tf(a0.x), f2tf(a0.y), f2tf(a0.z), f2tf(a0.w));
        *(uint4*)&As[0][(lr + 64) * 20 + lc] = make_uint4(f2tf(a1.x), f2tf(a1.y), f2tf(a1.z), f2tf(a1.w));
        *(uint4*)&Bs[0][lr * 20 + lc]        = make_uint4(f2tf(b0.x), f2tf(b0.y), f2tf(b0.z), f2tf(b0.w));
        *(uint4*)&Bs[0][(lr + 64) * 20 + lc] = make_uint4(f2tf(b1.x), f2tf(b1.y), f2tf(b1.z), f2tf(b1.w));
    }
    __syncthreads();

    const int NIT = K / 16;
    for (int it = 0; it < NIT; ++it) {
        const int cur = it & 1, nxt = cur ^ 1;
        float4 pa0, pa1, pb0, pb1;
        const bool pref = (it + 1 < NIT);
        if (pref) {
            const int off = (it + 1) * 16;
            pa0 = *(const float4*)(Ap0 + off);
            pa1 = *(const float4*)(Ap1 + off);
            pb0 = *(const float4*)(Wp0 + off);
            pb1 = *(const float4*)(Wp1 + off);
        }

        const unsigned aAddr = aAddr0 + cur * 10240;
        const unsigned bAddr = bAddr0 + cur * 10240;
#pragma unroll
        for (int ks = 0; ks < 16; ks += 8) {
            uint4 am[4], bp[2];
#pragma unroll
            for (int mt = 0; mt < 4; mt++)
                am[mt] = ldsm4(aAddr + ((mt * 320 + ks) << 2));
#pragma unroll
            for (int np = 0; np < 2; np++)
                bp[np] = ldsm4(bAddr + ((np * 320 + ks) << 2));
#pragma unroll
            for (int mt = 0; mt < 4; mt++) {
                const unsigned* a = (const unsigned*)&am[mt];
                mma8(acc[mt][0], a, bp[0].x, bp[0].y);
                mma8(acc[mt][1], a, bp[0].z, bp[0].w);
                mma8(acc[mt][2], a, bp[1].x, bp[1].y);
                mma8(acc[mt][3], a, bp[1].z, bp[1].w);
            }
        }

        if (pref) {
            *(uint4*)&As[nxt][lr * 20 + lc]        = make_uint4(f2tf(pa0.x), f2tf(pa0.y), f2tf(pa0.z), f2tf(pa0.w));
            *(uint4*)&As[nxt][(lr + 64) * 20 + lc] = make_uint4(f2tf(pa1.x), f2tf(pa1.y), f2tf(pa1.z), f2tf(pa1.w));
            *(uint4*)&Bs[nxt][lr * 20 + lc]        = make_uint4(f2tf(pb0.x), f2tf(pb0.y), f2tf(pb0.z), f2tf(pb0.w));
            *(uint4*)&Bs[nxt][(lr + 64) * 20 + lc] = make_uint4(f2tf(pb1.x), f2tf(pb1.y), f2tf(pb1.z), f2tf(pb1.w));
        }
        __syncthreads();
    }

#pragma unroll
    for (int mt = 0; mt < 4; mt++) {
        const int m = m0 + wm + mt * 16 + gid;
#pragma unroll
        for (int nt = 0; nt < 4; nt++) {
            const int n = n0 + wn + nt * 8 + 2 * tg;
            const float b0v = bias[n], b1v = bias[n + 1];
            float2 v0 = make_float2(acc[mt][nt][0] + b0v, acc[mt][nt][1] + b1v);
            float2 v1 = make_float2(acc[mt][nt][2] + b0v, acc[mt][nt][3] + b1v);
            if (MODE == 0) {
                *(float2*)&C[(long)m * N + n] = v0;
                *(float2*)&C[(long)(m + 8) * N + n] = v1;
            } else {
                const int b_ = m >> 11, s_ = m & 2047;
                const int h_ = n >> 6, d_ = n & 63;
                const long i0 = ((((long)(b_ * 16 + h_)) * SEQ + s_) << 6) + d_;
                *(float2*)&C[i0] = v0;
                *(float2*)&C[i0 + 512] = v1;
            }
        }
    }
}

// Fused Q/K/V projection: blockIdx.z selects which projection.
__global__ void __launch_bounds__(256, 2)
gemm_qkv(const float* __restrict__ x,
         const float* __restrict__ Wq, const float* __restrict__ bq,
         const float* __restrict__ Wk, const float* __restrict__ bk,
         const float* __restrict__ Wv, const float* __restrict__ bv,
         float* __restrict__ Q, float* __restrict__ K, float* __restrict__ V)
{
    const float* W; const float* b; float* C;
    if (blockIdx.z == 0)      { W = Wq; b = bq; C = Q; }
    else if (blockIdx.z == 1) { W = Wk; b = bk; C = K; }
    else                      { W = Wv; b = bv; C = V; }
    gemm_body<1>(x, W, b, C, MROWS, DMODEL, DMODEL, blockIdx.x, blockIdx.y);
}

__global__ void __launch_bounds__(256, 2)
gemm_out(const float* __restrict__ A, const float* __restrict__ W,
         const float* __restrict__ bias, float* __restrict__ C)
{
    gemm_body<0>(A, W, bias, C, MROWS, DMODEL, DMODEL, blockIdx.x, blockIdx.y);
}

// ---------------------------------------------------------------------------
// Flash attention, tf32 mma. 8 warps = 128 q rows per block; one shared
// K/V tile serves all 8 warps (halved fill traffic vs 4-warp version), and
// warps' exp (FMA/MUFU) overlaps other warps' mma (tensor).
// Dynamic smem layout (words):
//   KP[128*68] : rows 0-63 = K tile [ks][d]; after QK, rows 0-127 = P[q][ks]
//   Vf[8*576]  : V tile pre-scattered in mma B-fragment order
// ---------------------------------------------------------------------------
extern __shared__ unsigned smem_dyn[];

#define FLASH_SMEM_BYTES ((128 * 68 + 8 * 576) * 4)

__global__ void __launch_bounds__(256, 1)
flash_tf32(const float* __restrict__ Q, const float* __restrict__ K,
           const float* __restrict__ V, float* __restrict__ CTX)
{
    unsigned* KP = smem_dyn;             // 128*68 words
    unsigned* Vf = smem_dyn + 128 * 68;  // 8*576 words

    const int tid = threadIdx.x;
    const int lane = tid & 31, warp = tid >> 5;   // warp 0..7
    const int gid = lane >> 2, tg = lane & 3;
    const int bh = blockIdx.y, q0 = blockIdx.x * 128;

    const float* Qb = Q + ((long)bh * SEQ + q0 + warp * 16) * HDIM;
    const float* Kb = K + (long)bh * SEQ * HDIM;
    const float* Vb = V + (long)bh * SEQ * HDIM;

    const unsigned kpb = (unsigned)__cvta_generic_to_shared(KP);
    // QK^T B-frag ldmatrix address (K rows 0-63)
    const unsigned aqk = kpb + ((((lane >> 4) * 8 + (lane & 7)) * 68
                                 + ((lane >> 3) & 1) * 4) << 2);
    // P A-frag ldmatrix address (P rows warp*16 .. +15)
    const unsigned apa = kpb + (((warp * 16 + (lane & 7) + ((lane >> 3) & 1) * 8) * 68
                                 + ((lane >> 4) & 1) * 4) << 2);

    // Q fragments for all 8 k-chunks, in registers for the whole kernel
    unsigned qa[8][4];
    {
        const float* r0p = Qb + gid * HDIM;
        const float* r1p = Qb + (gid + 8) * HDIM;
#pragma unroll
        for (int kc = 0; kc < 8; kc++) {
            qa[kc][0] = f2tf(r0p[kc * 8 + tg]);
            qa[kc][1] = f2tf(r1p[kc * 8 + tg]);
            qa[kc][2] = f2tf(r0p[kc * 8 + tg + 4]);
            qa[kc][3] = f2tf(r1p[kc * 8 + tg + 4]);
        }
    }

    float oacc[8][4];
#pragma unroll
    for (int nt = 0; nt < 8; nt++)
#pragma unroll
        for (int i = 0; i < 4; i++) oacc[nt][i] = 0.0f;
    float l0 = 0.0f, l1 = 0.0f;
    const float S2 = 0.18033688011112042f;   // (1/8) * log2(e)

    const int prow0 = (warp * 16 + gid) * 68;
    const int prow1 = prow0 + 8 * 68;

    for (int kt = 0; kt < SEQ / 64; kt++) {
        __syncthreads();   // previous iteration's P / Vf reads done
        const float* Kt = Kb + kt * 64 * HDIM;
        const float* Vt = Vb + kt * 64 * HDIM;
#pragma unroll
        for (int j4 = 0; j4 < 4; j4++) {
            const int i = tid + j4 * 256;
            const int r = i >> 4, d4 = (i & 15) << 2;
            float4 kv = *(const float4*)(Kt + r * 64 + d4);
            *(uint4*)&KP[r * 68 + d4] = make_uint4(f2tf(kv.x), f2tf(kv.y), f2tf(kv.z), f2tf(kv.w));
            float4 vv = *(const float4*)(Vt + r * 64 + d4);
            const int vb = (r >> 3) * 576 + ((d4 & 7) * 4 + (r & 3)) * 18
                         + ((d4 >> 3) << 1) + ((r >> 2) & 1);
            Vf[vb]       = f2tf(vv.x);
            Vf[vb + 72]  = f2tf(vv.y);
            Vf[vb + 144] = f2tf(vv.z);
            Vf[vb + 216] = f2tf(vv.w);
        }
        __syncthreads();

        // S = Q @ K^T  (warp: 16q x 64k)
        float sacc[8][4];
#pragma unroll
        for (int nt = 0; nt < 8; nt++)
#pragma unroll
            for (int i = 0; i < 4; i++) sacc[nt][i] = 0.0f;
#pragma unroll
        for (int kc = 0; kc < 8; kc++) {
#pragma unroll
            for (int np = 0; np < 4; np++) {
                uint4 bb = ldsm4(aqk + ((np * 16 * 68 + kc * 8) << 2));
                mma8(sacc[2 * np],     qa[kc], bb.x, bb.y);
                mma8(sacc[2 * np + 1], qa[kc], bb.z, bb.w);
            }
        }
        __syncthreads();   // all warps done reading K; safe to overwrite with P

        // exp (hybrid MUFU/poly), row sums, store P (tf32) into KP region
#pragma unroll
        for (int nt = 0; nt < 8; nt++) {
            const float t0 = sacc[nt][0] * S2, t1 = sacc[nt][1] * S2;
            const float t2 = sacc[nt][2] * S2, t3 = sacc[nt][3] * S2;
            float p0, p1, p2, p3;
            if (nt & 1) {
                p0 = ex2_mufu(t0); p1 = ex2_mufu(t1);
                p2 = ex2_mufu(t2); p3 = ex2_mufu(t3);
            } else {
                p0 = ex2_poly(t0); p1 = ex2_poly(t1);
                p2 = ex2_poly(t2); p3 = ex2_poly(t3);
            }
            l0 += p0 + p1;
            l1 += p2 + p3;
            *(uint2*)&KP[prow0 + nt * 8 + 2 * tg] = make_uint2(f2tf(p0), f2tf(p1));
            *(uint2*)&KP[prow1 + nt * 8 + 2 * tg] = make_uint2(f2tf(p2), f2tf(p3));
        }
        __syncwarp();   // warp reads only its own 16 P rows

        // O += P @ V
#pragma unroll
        for (int kc = 0; kc < 8; kc++) {
            uint4 af4 = ldsm4(apa + ((kc * 8) << 2));
            const unsigned* a = (const unsigned*)&af4;
            const unsigned* vp = &Vf[kc * 576 + lane * 18];
#pragma unroll
            for (int nt = 0; nt < 8; nt++) {
                uint2 b = *(const uint2*)(vp + nt * 2);
                mma8(oacc[nt], a, b.x, b.y);
            }
        }
    }

    // finalize
    l0 += __shfl_xor_sync(0xffffffffu, l0, 1);
    l0 += __shfl_xor_sync(0xffffffffu, l0, 2);
    l1 += __shfl_xor_sync(0xffffffffu, l1, 1);
    l1 += __shfl_xor_sync(0xffffffffu, l1, 2);
    const float inv0 = 1.0f / l0, inv1 = 1.0f / l1;

    const int b = bh >> 4, h = bh & 15;
    float* base  = CTX + ((long)b * SEQ + q0 + warp * 16 + gid) * DMODEL + h * HDIM + 2 * tg;
    float* base8 = base + 8 * DMODEL;
#pragma unroll
    for (int nt = 0; nt < 8; nt++) {
        *(float2*)(base  + nt * 8) = make_float2(oacc[nt][0] * inv0, oacc[nt][1] * inv0);
        *(float2*)(base8 + nt * 8) = make_float2(oacc[nt][2] * inv1, oacc[nt][3] * inv1);
    }
}

// ---------------------------------------------------------------------------
// Launch
// ---------------------------------------------------------------------------
extern "C" void kernel_launch(void* const* d_in, const int* in_sizes, int n_in,
                              void* d_out, int out_size)
{
    const float* x  = (const float*)d_in[0];
    const float* Wq = (const float*)d_in[1];
    const float* bq = (const float*)d_in[2];
    const float* Wk = (const float*)d_in[3];
    const float* bk = (const float*)d_in[4];
    const float* Wv = (const float*)d_in[5];
    const float* bv = (const float*)d_in[6];
    const float* Wo = (const float*)d_in[7];
    const float* bo = (const float*)d_in[8];
    float* out = (float*)d_out;

    float *pQ, *pK, *pV, *pCTX;
    cudaGetSymbolAddress((void**)&pQ,   g_Q);
    cudaGetSymbolAddress((void**)&pK,   g_K);
    cudaGetSymbolAddress((void**)&pV,   g_V);
    cudaGetSymbolAddress((void**)&pCTX, g_CTX);

    cudaFuncSetAttribute(flash_tf32,
                         cudaFuncAttributeMaxDynamicSharedMemorySize,
                         FLASH_SMEM_BYTES);

    dim3 qkv_grid(DMODEL / 128, MROWS / 128, 3);   // (8, 32, 3)
    gemm_qkv<<<qkv_grid, 256>>>(x, Wq, bq, Wk, bk, Wv, bv, pQ, pK, pV);

    dim3 attn_grid(SEQ / 128, BATCH * NHEAD);      // (16, 32)
    flash_tf32<<<attn_grid, 256, FLASH_SMEM_BYTES>>>(pQ, pK, pV, pCTX);

    dim3 out_grid(DMODEL / 128, MROWS / 128);
    gemm_out<<<out_grid, 256>>>(pCTX, Wo, bo, out);
}

// round 8
// speedup vs baseline: 1.0254x; 1.0254x over previous
#include <cuda_runtime.h>

#define BATCH 2
#define SEQ   2048
#define DMODEL 1024
#define NHEAD 16
#define HDIM  64
#define MROWS (BATCH * SEQ)   // 4096

// ---------------------------------------------------------------------------
// Scratch
// ---------------------------------------------------------------------------
__device__ float g_Q[BATCH * NHEAD * SEQ * HDIM];    // [B,H,S,Hd]
__device__ float g_K[BATCH * NHEAD * SEQ * HDIM];
__device__ float g_V[BATCH * NHEAD * SEQ * HDIM];
__device__ float g_CTX[MROWS * DMODEL];              // [B,S,D]

// ---------------------------------------------------------------------------
// helpers
// ---------------------------------------------------------------------------
__device__ __forceinline__ unsigned f2tf(float x) {
    unsigned u;
    asm("cvt.rna.tf32.f32 %0, %1;" : "=r"(u) : "f"(x));
    return u;
}

__device__ __forceinline__ void mma8(float* c, const unsigned* a, unsigned b0, unsigned b1) {
    asm("mma.sync.aligned.m16n8k8.row.col.f32.tf32.tf32.f32 "
        "{%0,%1,%2,%3},{%4,%5,%6,%7},{%8,%9},{%0,%1,%2,%3};"
        : "+f"(c[0]), "+f"(c[1]), "+f"(c[2]), "+f"(c[3])
        : "r"(a[0]), "r"(a[1]), "r"(a[2]), "r"(a[3]), "r"(b0), "r"(b1));
}

__device__ __forceinline__ uint4 ldsm4(unsigned addr) {
    uint4 r;
    asm volatile("ldmatrix.sync.aligned.m8n8.x4.shared.b16 {%0,%1,%2,%3}, [%4];"
        : "=r"(r.x), "=r"(r.y), "=r"(r.z), "=r"(r.w) : "r"(addr));
    return r;
}

__device__ __forceinline__ float ex2_mufu(float t) {
    float y;
    asm("ex2.approx.f32 %0, %1;" : "=f"(y) : "f"(t));
    return y;
}
__device__ __forceinline__ float ex2_poly(float t) {
    const float C = 12582912.0f;  // 1.5 * 2^23
    float r = __fadd_rn(t, C);
    float f = __fsub_rn(t, __fsub_rn(r, C));
    unsigned sb = (((unsigned)__float_as_int(r)) << 23) + 0x3f800000u;
    float p = 0.0096181f;
    p = fmaf(p, f, 0.0554906f);
    p = fmaf(p, f, 0.2401597f);
    p = fmaf(p, f, 0.6931472f);
    p = fmaf(p, f, 1.0f);
    return p * __int_as_float((int)sb);
}

__device__ __forceinline__ void cpa16(unsigned dst, const void* src) {
    asm volatile("cp.async.cg.shared.global [%0], [%1], 16;" :: "r"(dst), "l"(src));
}
__device__ __forceinline__ void cpa_commit() {
    asm volatile("cp.async.commit_group;" ::: "memory");
}
__device__ __forceinline__ void cpa_wait0() {
    asm volatile("cp.async.wait_group 0;" ::: "memory");
}

// ---------------------------------------------------------------------------
// tf32 GEMM (round-5 known-good): C[M,N] = A[M,K] @ W[N,K]^T + bias[N]
// Block 128x128, BK=16, 256 threads (8 warps 2x4), warp tile 64x32.
// Fragment loads via ldmatrix.x4 (ld=20: conflict-free, 16B-aligned rows).
// ---------------------------------------------------------------------------
template<int MODE>
__device__ __forceinline__ void gemm_body(
    const float* __restrict__ A, const float* __restrict__ W,
    const float* __restrict__ bias, float* __restrict__ C,
    int M, int N, int K, int bx, int by)
{
    __shared__ __align__(16) unsigned As[128 * 20];
    __shared__ __align__(16) unsigned Bs[128 * 20];

    const int tid = threadIdx.x;
    const int lane = tid & 31, warp = tid >> 5;
    const int gid = lane >> 2, tg = lane & 3;
    const int m0 = by * 128, n0 = bx * 128;
    const int wm = (warp >> 2) * 64, wn = (warp & 3) * 32;

    const int lr = tid >> 2;           // 0..63
    const int lc = (tid & 3) << 2;     // 0,4,8,12
    const float* Ap0 = A + (long)(m0 + lr) * K + lc;
    const float* Ap1 = A + (long)(m0 + lr + 64) * K + lc;
    const float* Wp0 = W + (long)(n0 + lr) * K + lc;
    const float* Wp1 = W + (long)(n0 + lr + 64) * K + lc;

    const unsigned sA = (unsigned)__cvta_generic_to_shared(As);
    const unsigned sB = (unsigned)__cvta_generic_to_shared(Bs);
    const unsigned aAddr = sA + (((wm + (lane & 7) + ((lane >> 3) & 1) * 8) * 20
                                  + ((lane >> 4) & 1) * 4) << 2);
    const unsigned bAddr = sB + (((wn + (lane >> 4) * 8 + (lane & 7)) * 20
                                  + ((lane >> 3) & 1) * 4) << 2);

    float acc[4][4][4];
#pragma unroll
    for (int mt = 0; mt < 4; mt++)
#pragma unroll
        for (int nt = 0; nt < 4; nt++)
#pragma unroll
            for (int i = 0; i < 4; i++) acc[mt][nt][i] = 0.0f;

    float4 pa0 = *(const float4*)Ap0;
    float4 pa1 = *(const float4*)Ap1;
    float4 pb0 = *(const float4*)Wp0;
    float4 pb1 = *(const float4*)Wp1;

    const int NIT = K / 16;
    for (int it = 0; it < NIT; ++it) {
        __syncthreads();
        *(uint4*)&As[lr * 20 + lc]        = make_uint4(f2tf(pa0.x), f2tf(pa0.y), f2tf(pa0.z), f2tf(pa0.w));
        *(uint4*)&As[(lr + 64) * 20 + lc] = make_uint4(f2tf(pa1.x), f2tf(pa1.y), f2tf(pa1.z), f2tf(pa1.w));
        *(uint4*)&Bs[lr * 20 + lc]        = make_uint4(f2tf(pb0.x), f2tf(pb0.y), f2tf(pb0.z), f2tf(pb0.w));
        *(uint4*)&Bs[(lr + 64) * 20 + lc] = make_uint4(f2tf(pb1.x), f2tf(pb1.y), f2tf(pb1.z), f2tf(pb1.w));
        __syncthreads();
        if (it + 1 < NIT) {
            const int off = (it + 1) * 16;
            pa0 = *(const float4*)(Ap0 + off);
            pa1 = *(const float4*)(Ap1 + off);
            pb0 = *(const float4*)(Wp0 + off);
            pb1 = *(const float4*)(Wp1 + off);
        }
#pragma unroll
        for (int ks = 0; ks < 16; ks += 8) {
            uint4 am[4], bp[2];
#pragma unroll
            for (int mt = 0; mt < 4; mt++)
                am[mt] = ldsm4(aAddr + ((mt * 320 + ks) << 2));
#pragma unroll
            for (int np = 0; np < 2; np++)
                bp[np] = ldsm4(bAddr + ((np * 320 + ks) << 2));
#pragma unroll
            for (int mt = 0; mt < 4; mt++) {
                const unsigned* a = (const unsigned*)&am[mt];
                mma8(acc[mt][0], a, bp[0].x, bp[0].y);
                mma8(acc[mt][1], a, bp[0].z, bp[0].w);
                mma8(acc[mt][2], a, bp[1].x, bp[1].y);
                mma8(acc[mt][3], a, bp[1].z, bp[1].w);
            }
        }
    }

#pragma unroll
    for (int mt = 0; mt < 4; mt++) {
        const int m = m0 + wm + mt * 16 + gid;
#pragma unroll
        for (int nt = 0; nt < 4; nt++) {
            const int n = n0 + wn + nt * 8 + 2 * tg;
            const float b0v = bias[n], b1v = bias[n + 1];
            float2 v0 = make_float2(acc[mt][nt][0] + b0v, acc[mt][nt][1] + b1v);
            float2 v1 = make_float2(acc[mt][nt][2] + b0v, acc[mt][nt][3] + b1v);
            if (MODE == 0) {
                *(float2*)&C[(long)m * N + n] = v0;
                *(float2*)&C[(long)(m + 8) * N + n] = v1;
            } else {
                const int b_ = m >> 11, s_ = m & 2047;
                const int h_ = n >> 6, d_ = n & 63;
                const long i0 = ((((long)(b_ * 16 + h_)) * SEQ + s_) << 6) + d_;
                *(float2*)&C[i0] = v0;
                *(float2*)&C[i0 + 512] = v1;
            }
        }
    }
}

__global__ void __launch_bounds__(256)
gemm_qkv(const float* __restrict__ x,
         const float* __restrict__ Wq, const float* __restrict__ bq,
         const float* __restrict__ Wk, const float* __restrict__ bk,
         const float* __restrict__ Wv, const float* __restrict__ bv,
         float* __restrict__ Q, float* __restrict__ K, float* __restrict__ V)
{
    const float* W; const float* b; float* C;
    if (blockIdx.z == 0)      { W = Wq; b = bq; C = Q; }
    else if (blockIdx.z == 1) { W = Wk; b = bk; C = K; }
    else                      { W = Wv; b = bv; C = V; }
    gemm_body<1>(x, W, b, C, MROWS, DMODEL, DMODEL, blockIdx.x, blockIdx.y);
}

__global__ void __launch_bounds__(256)
gemm_out(const float* __restrict__ A, const float* __restrict__ W,
         const float* __restrict__ bias, float* __restrict__ C)
{
    gemm_body<0>(A, W, bias, C, MROWS, DMODEL, DMODEL, blockIdx.x, blockIdx.y);
}

// ---------------------------------------------------------------------------
// Flash attention, tf32 mma, 4 warps = 64 q rows per block.
// cp.async stages the NEXT K/V tile (raw fp32) into smem while the current
// tile's QK/softmax/PV compute runs; the convert/scatter phase reads smem.
// Dynamic smem words:
//   Ks  [64*68]  K tile tf32 [ks][d] (ld=68), reused as P[q][ks]
//   Vf  [8*576]  V tile tf32 pre-scattered in mma B-fragment order
//   Kraw[64*64]f V raw staging   Vraw[64*64]f
// ---------------------------------------------------------------------------
#define FL_KS   0
#define FL_VF   (64 * 68)
#define FL_KRAW (FL_VF + 8 * 576)
#define FL_VRAW (FL_KRAW + 64 * 64)
#define FL_WORDS (FL_VRAW + 64 * 64)
#define FL_BYTES (FL_WORDS * 4)

extern __shared__ unsigned fsm[];

__global__ void __launch_bounds__(128)
flash_tf32(const float* __restrict__ Q, const float* __restrict__ K,
           const float* __restrict__ V, float* __restrict__ CTX)
{
    unsigned* Ks = fsm + FL_KS;
    unsigned* Vf = fsm + FL_VF;
    float* Kraw = (float*)(fsm + FL_KRAW);
    float* Vraw = (float*)(fsm + FL_VRAW);

    const int tid = threadIdx.x;
    const int lane = tid & 31, warp = tid >> 5;
    const int gid = lane >> 2, tg = lane & 3;
    const int bh = blockIdx.y, q0 = blockIdx.x * 64;

    const float* Qb = Q + ((long)bh * SEQ + q0 + warp * 16) * HDIM;
    const float* Kb = K + (long)bh * SEQ * HDIM;
    const float* Vb = V + (long)bh * SEQ * HDIM;

    const unsigned smb  = (unsigned)__cvta_generic_to_shared(fsm);
    const unsigned ksb  = smb + FL_KS * 4;
    const unsigned krb  = smb + FL_KRAW * 4;
    const unsigned vrb  = smb + FL_VRAW * 4;
    // QK^T B-frag ldmatrix address
    const unsigned aqk = ksb + ((((lane >> 4) * 8 + (lane & 7)) * 68
                                 + ((lane >> 3) & 1) * 4) << 2);
    // P A-frag ldmatrix address
    const unsigned apa = ksb + (((warp * 16 + (lane & 7) + ((lane >> 3) & 1) * 8) * 68
                                 + ((lane >> 4) & 1) * 4) << 2);

    // stage tile 0 (overlaps the Q fragment loads below)
    {
        const char* Kc = (const char*)Kb;
        const char* Vc = (const char*)Vb;
#pragma unroll
        for (int j = 0; j < 8; j++) {
            const unsigned off = (unsigned)(tid + j * 128) * 16;
            cpa16(krb + off, Kc + off);
            cpa16(vrb + off, Vc + off);
        }
        cpa_commit();
    }

    // Q fragments for all 8 k-chunks, in registers for the whole kernel
    unsigned qa[8][4];
    {
        const float* r0p = Qb + gid * HDIM;
        const float* r1p = Qb + (gid + 8) * HDIM;
#pragma unroll
        for (int kc = 0; kc < 8; kc++) {
            qa[kc][0] = f2tf(r0p[kc * 8 + tg]);
            qa[kc][1] = f2tf(r1p[kc * 8 + tg]);
            qa[kc][2] = f2tf(r0p[kc * 8 + tg + 4]);
            qa[kc][3] = f2tf(r1p[kc * 8 + tg + 4]);
        }
    }

    float oacc[8][4];
#pragma unroll
    for (int nt = 0; nt < 8; nt++)
#pragma unroll
        for (int i = 0; i < 4; i++) oacc[nt][i] = 0.0f;
    float l0 = 0.0f, l1 = 0.0f;
    const float S2 = 0.18033688011112042f;   // (1/8) * log2(e)

    const int prow0 = (warp * 16 + gid) * 68;
    const int prow1 = prow0 + 8 * 68;

    for (int kt = 0; kt < SEQ / 64; kt++) {
        cpa_wait0();       // tile kt resident in Kraw/Vraw
        __syncthreads();   // raw visible to all; prior iter's Ks/Vf reads done

        // convert + scatter from smem staging
#pragma unroll
        for (int j8 = 0; j8 < 8; j8++) {
            const int i = tid + j8 * 128;
            const int r = i >> 4, d4 = (i & 15) << 2;
            float4 kv = *(const float4*)&Kraw[r * 64 + d4];
            *(uint4*)&Ks[r * 68 + d4] = make_uint4(f2tf(kv.x), f2tf(kv.y), f2tf(kv.z), f2tf(kv.w));
            float4 vv = *(const float4*)&Vraw[r * 64 + d4];
            const int vb = (r >> 3) * 576 + ((d4 & 7) * 4 + (r & 3)) * 18
                         + ((d4 >> 3) << 1) + ((r >> 2) & 1);
            Vf[vb]       = f2tf(vv.x);
            Vf[vb + 72]  = f2tf(vv.y);
            Vf[vb + 144] = f2tf(vv.z);
            Vf[vb + 216] = f2tf(vv.w);
        }
        __syncthreads();   // conversions visible; all raw reads done

        // stage tile kt+1 (async; overlaps QK/exp/PV below)
        if (kt + 1 < SEQ / 64) {
            const char* Kc = (const char*)(Kb + (kt + 1) * 64 * HDIM);
            const char* Vc = (const char*)(Vb + (kt + 1) * 64 * HDIM);
#pragma unroll
            for (int j = 0; j < 8; j++) {
                const unsigned off = (unsigned)(tid + j * 128) * 16;
                cpa16(krb + off, Kc + off);
                cpa16(vrb + off, Vc + off);
            }
            cpa_commit();
        } else {
            cpa_commit();  // empty group so wait_group 0 at loop top stays cheap
        }

        // S = Q @ K^T  (warp: 16q x 64k)
        float sacc[8][4];
#pragma unroll
        for (int nt = 0; nt < 8; nt++)
#pragma unroll
            for (int i = 0; i < 4; i++) sacc[nt][i] = 0.0f;
#pragma unroll
        for (int kc = 0; kc < 8; kc++) {
#pragma unroll
            for (int np = 0; np < 4; np++) {
                uint4 bb = ldsm4(aqk + ((np * 16 * 68 + kc * 8) << 2));
                mma8(sacc[2 * np],     qa[kc], bb.x, bb.y);
                mma8(sacc[2 * np + 1], qa[kc], bb.z, bb.w);
            }
        }
        __syncthreads();   // all warps done reading Ks; safe to overwrite with P

        // exp (3/8 poly on FMA pipe, 5/8 MUFU), row sums, store P tf32
#pragma unroll
        for (int nt = 0; nt < 8; nt++) {
            const float t0 = sacc[nt][0] * S2, t1 = sacc[nt][1] * S2;
            const float t2 = sacc[nt][2] * S2, t3 = sacc[nt][3] * S2;
            float p0, p1, p2, p3;
            if (nt == 0 || nt == 3 || nt == 6) {
                p0 = ex2_poly(t0); p1 = ex2_poly(t1);
                p2 = ex2_poly(t2); p3 = ex2_poly(t3);
            } else {
                p0 = ex2_mufu(t0); p1 = ex2_mufu(t1);
                p2 = ex2_mufu(t2); p3 = ex2_mufu(t3);
            }
            l0 += p0 + p1;
            l1 += p2 + p3;
            *(uint2*)&Ks[prow0 + nt * 8 + 2 * tg] = make_uint2(f2tf(p0), f2tf(p1));
            *(uint2*)&Ks[prow1 + nt * 8 + 2 * tg] = make_uint2(f2tf(p2), f2tf(p3));
        }
        __syncwarp();      // warp reads only its own 16 P rows

        // O += P @ V
#pragma unroll
        for (int kc = 0; kc < 8; kc++) {
            uint4 af4 = ldsm4(apa + ((kc * 8) << 2));
            const unsigned* a = (const unsigned*)&af4;
            const unsigned* vp = &Vf[kc * 576 + lane * 18];
#pragma unroll
            for (int nt = 0; nt < 8; nt++) {
                uint2 b = *(const uint2*)(vp + nt * 2);
                mma8(oacc[nt], a, b.x, b.y);
            }
        }
    }

    // finalize
    l0 += __shfl_xor_sync(0xffffffffu, l0, 1);
    l0 += __shfl_xor_sync(0xffffffffu, l0, 2);
    l1 += __shfl_xor_sync(0xffffffffu, l1, 1);
    l1 += __shfl_xor_sync(0xffffffffu, l1, 2);
    const float inv0 = 1.0f / l0, inv1 = 1.0f / l1;

    const int b = bh >> 4, h = bh & 15;
    float* base  = CTX + ((long)b * SEQ + q0 + warp * 16 + gid) * DMODEL + h * HDIM + 2 * tg;
    float* base8 = base + 8 * DMODEL;
#pragma unroll
    for (int nt = 0; nt < 8; nt++) {
        *(float2*)(base  + nt * 8) = make_float2(oacc[nt][0] * inv0, oacc[nt][1] * inv0);
        *(float2*)(base8 + nt * 8) = make_float2(oacc[nt][2] * inv1, oacc[nt][3] * inv1);
    }
}

// ---------------------------------------------------------------------------
// Launch
// ---------------------------------------------------------------------------
extern "C" void kernel_launch(void* const* d_in, const int* in_sizes, int n_in,
                              void* d_out, int out_size)
{
    const float* x  = (const float*)d_in[0];
    const float* Wq = (const float*)d_in[1];
    const float* bq = (const float*)d_in[2];
    const float* Wk = (const float*)d_in[3];
    const float* bk = (const float*)d_in[4];
    const float* Wv = (const float*)d_in[5];
    const float* bv = (const float*)d_in[6];
    const float* Wo = (const float*)d_in[7];
    const float* bo = (const float*)d_in[8];
    float* out = (float*)d_out;

    float *pQ, *pK, *pV, *pCTX;
    cudaGetSymbolAddress((void**)&pQ,   g_Q);
    cudaGetSymbolAddress((void**)&pK,   g_K);
    cudaGetSymbolAddress((void**)&pV,   g_V);
    cudaGetSymbolAddress((void**)&pCTX, g_CTX);

    cudaFuncSetAttribute(flash_tf32,
                         cudaFuncAttributeMaxDynamicSharedMemorySize, FL_BYTES);

    dim3 qkv_grid(DMODEL / 128, MROWS / 128, 3);   // (8, 32, 3)
    gemm_qkv<<<qkv_grid, 256>>>(x, Wq, bq, Wk, bk, Wv, bv, pQ, pK, pV);

    dim3 attn_grid(SEQ / 64, BATCH * NHEAD);       // (32, 32)
    flash_tf32<<<attn_grid, 128, FL_BYTES>>>(pQ, pK, pV, pCTX);

    dim3 out_grid(DMODEL / 128, MROWS / 128);      // (8, 32)
    gemm_out<<<out_grid, 256>>>(pCTX, Wo, bo, out);
}

// round 9
// speedup vs baseline: 1.7656x; 1.7218x over previous
#include <cuda_runtime.h>

#define BATCH 2
#define SEQ   2048
#define DMODEL 1024
#define NHEAD 16
#define HDIM  64
#define MROWS (BATCH * SEQ)   // 4096

// ---------------------------------------------------------------------------
// Scratch
// ---------------------------------------------------------------------------
__device__ float g_Q[BATCH * NHEAD * SEQ * HDIM];    // [B,H,S,Hd]
__device__ float g_K[BATCH * NHEAD * SEQ * HDIM];
__device__ float g_V[BATCH * NHEAD * SEQ * HDIM];
__device__ float g_CTX[MROWS * DMODEL];              // [B,S,D]

// ---------------------------------------------------------------------------
// helpers
// ---------------------------------------------------------------------------
__device__ __forceinline__ unsigned f2h2(float lo, float hi) {
    unsigned r;
    asm("cvt.rn.f16x2.f32 %0, %1, %2;" : "=r"(r) : "f"(hi), "f"(lo));
    return r;
}

// D(16x8,f32) += A(16x16 f16,row) * B(16x8 f16,col)
__device__ __forceinline__ void mma16(float* c, const unsigned* a, unsigned b0, unsigned b1) {
    asm("mma.sync.aligned.m16n8k16.row.col.f32.f16.f16.f32 "
        "{%0,%1,%2,%3},{%4,%5,%6,%7},{%8,%9},{%0,%1,%2,%3};"
        : "+f"(c[0]), "+f"(c[1]), "+f"(c[2]), "+f"(c[3])
        : "r"(a[0]), "r"(a[1]), "r"(a[2]), "r"(a[3]), "r"(b0), "r"(b1));
}

__device__ __forceinline__ uint4 ldsm4(unsigned addr) {
    uint4 r;
    asm volatile("ldmatrix.sync.aligned.m8n8.x4.shared.b16 {%0,%1,%2,%3}, [%4];"
        : "=r"(r.x), "=r"(r.y), "=r"(r.z), "=r"(r.w) : "r"(addr));
    return r;
}
__device__ __forceinline__ uint4 ldsm4t(unsigned addr) {
    uint4 r;
    asm volatile("ldmatrix.sync.aligned.m8n8.x4.trans.shared.b16 {%0,%1,%2,%3}, [%4];"
        : "=r"(r.x), "=r"(r.y), "=r"(r.z), "=r"(r.w) : "r"(addr));
    return r;
}

__device__ __forceinline__ float ex2_mufu(float t) {
    float y;
    asm("ex2.approx.f32 %0, %1;" : "=f"(y) : "f"(t));
    return y;
}
__device__ __forceinline__ float ex2_poly(float t) {
    const float C = 12582912.0f;  // 1.5 * 2^23
    float r = __fadd_rn(t, C);
    float f = __fsub_rn(t, __fsub_rn(r, C));
    unsigned sb = (((unsigned)__float_as_int(r)) << 23) + 0x3f800000u;
    float p = 0.0096181f;
    p = fmaf(p, f, 0.0554906f);
    p = fmaf(p, f, 0.2401597f);
    p = fmaf(p, f, 0.6931472f);
    p = fmaf(p, f, 1.0f);
    return p * __int_as_float((int)sb);
}

// ---------------------------------------------------------------------------
// fp16 GEMM: C[M,N] = A[M,K] @ W[N,K]^T + bias[N]
// Block 128x128, BK=16, 256 threads (8 warps 2x4), warp tile 64x32.
// Smem tiles fp16, pitch 24 halves (48B): ldsm rows 16B-aligned,
// 3r mod 8 distinct -> conflict-free. Per iter: 6 ldsm + 16 mma16.
// ---------------------------------------------------------------------------
template<int MODE>
__device__ __forceinline__ void gemm_body(
    const float* __restrict__ A, const float* __restrict__ W,
    const float* __restrict__ bias, float* __restrict__ C,
    int M, int N, int K, int bx, int by)
{
    __shared__ __align__(16) unsigned short As[128 * 24];
    __shared__ __align__(16) unsigned short Bs[128 * 24];

    const int tid = threadIdx.x;
    const int lane = tid & 31, warp = tid >> 5;
    const int gid = lane >> 2, tg = lane & 3;
    const int m0 = by * 128, n0 = bx * 128;
    const int wm = (warp >> 2) * 64, wn = (warp & 3) * 32;

    const int lr = tid >> 2;           // 0..63
    const int lc = (tid & 3) << 2;     // 0,4,8,12
    const float* Ap0 = A + (long)(m0 + lr) * K + lc;
    const float* Ap1 = A + (long)(m0 + lr + 64) * K + lc;
    const float* Wp0 = W + (long)(n0 + lr) * K + lc;
    const float* Wp1 = W + (long)(n0 + lr + 64) * K + lc;

    const unsigned sA = (unsigned)__cvta_generic_to_shared(As);
    const unsigned sB = (unsigned)__cvta_generic_to_shared(Bs);
    // A frag addr: m0=r0-7@k0, m1=r8-15@k0, m2=r0-7@k8, m3=r8-15@k8
    const unsigned aAddr = sA + (unsigned)((wm + (lane & 7) + ((lane >> 3) & 1) * 8) * 48
                                           + ((lane >> 4) & 1) * 16);
    // B frag addr: m0=n0-7@k0, m1=n0-7@k8, m2=n8-15@k0, m3=n8-15@k8
    const unsigned bAddr = sB + (unsigned)((wn + (lane >> 4) * 8 + (lane & 7)) * 48
                                           + ((lane >> 3) & 1) * 16);

    float acc[4][4][4];
#pragma unroll
    for (int mt = 0; mt < 4; mt++)
#pragma unroll
        for (int nt = 0; nt < 4; nt++)
#pragma unroll
            for (int i = 0; i < 4; i++) acc[mt][nt][i] = 0.0f;

    float4 pa0 = *(const float4*)Ap0;
    float4 pa1 = *(const float4*)Ap1;
    float4 pb0 = *(const float4*)Wp0;
    float4 pb1 = *(const float4*)Wp1;

    const int NIT = K / 16;
    for (int it = 0; it < NIT; ++it) {
        __syncthreads();
        *(uint2*)&As[lr * 24 + lc]        = make_uint2(f2h2(pa0.x, pa0.y), f2h2(pa0.z, pa0.w));
        *(uint2*)&As[(lr + 64) * 24 + lc] = make_uint2(f2h2(pa1.x, pa1.y), f2h2(pa1.z, pa1.w));
        *(uint2*)&Bs[lr * 24 + lc]        = make_uint2(f2h2(pb0.x, pb0.y), f2h2(pb0.z, pb0.w));
        *(uint2*)&Bs[(lr + 64) * 24 + lc] = make_uint2(f2h2(pb1.x, pb1.y), f2h2(pb1.z, pb1.w));
        __syncthreads();
        if (it + 1 < NIT) {
            const int off = (it + 1) * 16;
            pa0 = *(const float4*)(Ap0 + off);
            pa1 = *(const float4*)(Ap1 + off);
            pb0 = *(const float4*)(Wp0 + off);
            pb1 = *(const float4*)(Wp1 + off);
        }
        uint4 am[4], bp[2];
#pragma unroll
        for (int mt = 0; mt < 4; mt++)
            am[mt] = ldsm4(aAddr + mt * 768);          // 16 rows * 48B
#pragma unroll
        for (int np = 0; np < 2; np++)
            bp[np] = ldsm4(bAddr + np * 768);
#pragma unroll
        for (int mt = 0; mt < 4; mt++) {
            const unsigned* a = (const unsigned*)&am[mt];
            mma16(acc[mt][0], a, bp[0].x, bp[0].y);
            mma16(acc[mt][1], a, bp[0].z, bp[0].w);
            mma16(acc[mt][2], a, bp[1].x, bp[1].y);
            mma16(acc[mt][3], a, bp[1].z, bp[1].w);
        }
    }

#pragma unroll
    for (int mt = 0; mt < 4; mt++) {
        const int m = m0 + wm + mt * 16 + gid;
#pragma unroll
        for (int nt = 0; nt < 4; nt++) {
            const int n = n0 + wn + nt * 8 + 2 * tg;
            const float b0v = bias[n], b1v = bias[n + 1];
            float2 v0 = make_float2(acc[mt][nt][0] + b0v, acc[mt][nt][1] + b1v);
            float2 v1 = make_float2(acc[mt][nt][2] + b0v, acc[mt][nt][3] + b1v);
            if (MODE == 0) {
                *(float2*)&C[(long)m * N + n] = v0;
                *(float2*)&C[(long)(m + 8) * N + n] = v1;
            } else {
                const int b_ = m >> 11, s_ = m & 2047;
                const int h_ = n >> 6, d_ = n & 63;
                const long i0 = ((((long)(b_ * 16 + h_)) * SEQ + s_) << 6) + d_;
                *(float2*)&C[i0] = v0;
                *(float2*)&C[i0 + 512] = v1;
            }
        }
    }
}

__global__ void __launch_bounds__(256)
gemm_qkv(const float* __restrict__ x,
         const float* __restrict__ Wq, const float* __restrict__ bq,
         const float* __restrict__ Wk, const float* __restrict__ bk,
         const float* __restrict__ Wv, const float* __restrict__ bv,
         float* __restrict__ Q, float* __restrict__ K, float* __restrict__ V)
{
    const float* W; const float* b; float* C;
    if (blockIdx.z == 0)      { W = Wq; b = bq; C = Q; }
    else if (blockIdx.z == 1) { W = Wk; b = bk; C = K; }
    else                      { W = Wv; b = bv; C = V; }
    gemm_body<1>(x, W, b, C, MROWS, DMODEL, DMODEL, blockIdx.x, blockIdx.y);
}

__global__ void __launch_bounds__(256)
gemm_out(const float* __restrict__ A, const float* __restrict__ W,
         const float* __restrict__ bias, float* __restrict__ C)
{
    gemm_body<0>(A, W, bias, C, MROWS, DMODEL, DMODEL, blockIdx.x, blockIdx.y);
}

// ---------------------------------------------------------------------------
// Flash attention, fp16 mma, 4 warps = 64 q rows per block.
// Ks[ks][d] / Vs[ks][d] fp16, pitch 72 halves (144B: 9r mod 8 -> cf).
// QK B-frags: ldsm non-trans on Ks. PV B-frags: ldsm.trans on Vs.
// P NEVER touches smem: QK C-fragment n-pairs (2tg,2tg+1) pack directly
// into PV A-fragment k-pairs as half2 after exp.
// Per K-tile: 32 ldsm + 64 mma16 + 2 barriers.
// ---------------------------------------------------------------------------
__global__ void __launch_bounds__(128)
flash_h16(const float* __restrict__ Q, const float* __restrict__ K,
          const float* __restrict__ V, float* __restrict__ CTX)
{
    __shared__ __align__(16) unsigned short Ks[64 * 72];
    __shared__ __align__(16) unsigned short Vs[64 * 72];

    const int tid = threadIdx.x;
    const int lane = tid & 31, warp = tid >> 5;
    const int gid = lane >> 2, tg = lane & 3;
    const int bh = blockIdx.y, q0 = blockIdx.x * 64;

    const float* Qb = Q + ((long)bh * SEQ + q0 + warp * 16) * HDIM;
    const float* Kb = K + (long)bh * SEQ * HDIM;
    const float* Vb = V + (long)bh * SEQ * HDIM;

    const unsigned ksb = (unsigned)__cvta_generic_to_shared(Ks);
    const unsigned vsb = (unsigned)__cvta_generic_to_shared(Vs);
    // QK B-frag: m0=ks(np block) rows@d0-7, m1=@d8-15, m2=rows+8@d0-7, m3=+8@d8-15
    const unsigned aqk = ksb + (unsigned)(((lane >> 4) * 8 + (lane & 7)) * 144
                                          + ((lane >> 3) & 1) * 16);
    // PV B-frag (trans): lane gives row k = base + ((l>>3)&1)*8 + (l&7), col d block (l>>4)*8
    const unsigned avp = vsb + (unsigned)((((lane >> 3) & 1) * 8 + (lane & 7)) * 144
                                          + (lane >> 4) * 16);

    // Q A-fragments for the 4 k16 chunks, held in registers all kernel
    unsigned qa[4][4];
    {
        const float* r0p = Qb + gid * HDIM;
        const float* r1p = Qb + (gid + 8) * HDIM;
#pragma unroll
        for (int kc = 0; kc < 4; kc++) {
            const int k0 = kc * 16 + 2 * tg;
            qa[kc][0] = f2h2(r0p[k0],     r0p[k0 + 1]);
            qa[kc][1] = f2h2(r1p[k0],     r1p[k0 + 1]);
            qa[kc][2] = f2h2(r0p[k0 + 8], r0p[k0 + 9]);
            qa[kc][3] = f2h2(r1p[k0 + 8], r1p[k0 + 9]);
        }
    }

    float oacc[8][4];
#pragma unroll
    for (int nt = 0; nt < 8; nt++)
#pragma unroll
        for (int i = 0; i < 4; i++) oacc[nt][i] = 0.0f;
    float l0 = 0.0f, l1 = 0.0f;
    const float S2 = 0.18033688011112042f;   // (1/8) * log2(e)

    for (int kt = 0; kt < SEQ / 64; kt++) {
        __syncthreads();   // previous iteration's Ks/Vs reads done
        const float* Kt = Kb + kt * 64 * HDIM;
        const float* Vt = Vb + kt * 64 * HDIM;
#pragma unroll
        for (int j4 = 0; j4 < 4; j4++) {
            const int i = tid + j4 * 128;
            const int r = i >> 3, cs = (i & 7) * 8;
            float4 k0 = *(const float4*)(Kt + r * 64 + cs);
            float4 k1 = *(const float4*)(Kt + r * 64 + cs + 4);
            *(uint4*)&Ks[r * 72 + cs] = make_uint4(f2h2(k0.x, k0.y), f2h2(k0.z, k0.w),
                                                   f2h2(k1.x, k1.y), f2h2(k1.z, k1.w));
            float4 v0 = *(const float4*)(Vt + r * 64 + cs);
            float4 v1 = *(const float4*)(Vt + r * 64 + cs + 4);
            *(uint4*)&Vs[r * 72 + cs] = make_uint4(f2h2(v0.x, v0.y), f2h2(v0.z, v0.w),
                                                   f2h2(v1.x, v1.y), f2h2(v1.z, v1.w));
        }
        __syncthreads();

        // S = Q @ K^T  (warp: 16q x 64ks)
        float sacc[8][4];
#pragma unroll
        for (int nt = 0; nt < 8; nt++)
#pragma unroll
            for (int i = 0; i < 4; i++) sacc[nt][i] = 0.0f;
#pragma unroll
        for (int kc = 0; kc < 4; kc++) {
#pragma unroll
            for (int np = 0; np < 4; np++) {
                uint4 bb = ldsm4(aqk + (unsigned)(np * 16 * 144 + kc * 32));
                mma16(sacc[2 * np],     qa[kc], bb.x, bb.y);
                mma16(sacc[2 * np + 1], qa[kc], bb.z, bb.w);
            }
        }

        // exp (registers only): pack P directly into PV A-fragments
        unsigned ph[8][2];
#pragma unroll
        for (int nt = 0; nt < 8; nt++) {
            const float t0 = sacc[nt][0] * S2, t1 = sacc[nt][1] * S2;
            const float t2 = sacc[nt][2] * S2, t3 = sacc[nt][3] * S2;
            float p0, p1, p2, p3;
            if (nt == 0 || nt == 3 || nt == 6) {
                p0 = ex2_poly(t0); p1 = ex2_poly(t1);
                p2 = ex2_poly(t2); p3 = ex2_poly(t3);
            } else {
                p0 = ex2_mufu(t0); p1 = ex2_mufu(t1);
                p2 = ex2_mufu(t2); p3 = ex2_mufu(t3);
            }
            l0 += p0 + p1;
            l1 += p2 + p3;
            ph[nt][0] = f2h2(p0, p1);   // row gid,   ks pair
            ph[nt][1] = f2h2(p2, p3);   // row gid+8, ks pair
        }

        // O += P @ V   (A-frags from ph, B-frags via ldsm.trans on Vs)
#pragma unroll
        for (int kc = 0; kc < 4; kc++) {
            unsigned a[4] = { ph[2 * kc][0], ph[2 * kc][1],
                              ph[2 * kc + 1][0], ph[2 * kc + 1][1] };
#pragma unroll
            for (int np = 0; np < 4; np++) {
                uint4 bb = ldsm4t(avp + (unsigned)(kc * 16 * 144 + np * 32));
                mma16(oacc[2 * np],     a, bb.x, bb.y);
                mma16(oacc[2 * np + 1], a, bb.z, bb.w);
            }
        }
    }

    // finalize: quad-reduce row sums, normalize, write [B,S,D]
    l0 += __shfl_xor_sync(0xffffffffu, l0, 1);
    l0 += __shfl_xor_sync(0xffffffffu, l0, 2);
    l1 += __shfl_xor_sync(0xffffffffu, l1, 1);
    l1 += __shfl_xor_sync(0xffffffffu, l1, 2);
    const float inv0 = 1.0f / l0, inv1 = 1.0f / l1;

    const int b = bh >> 4, h = bh & 15;
    float* base  = CTX + ((long)b * SEQ + q0 + warp * 16 + gid) * DMODEL + h * HDIM + 2 * tg;
    float* base8 = base + 8 * DMODEL;
#pragma unroll
    for (int nt = 0; nt < 8; nt++) {
        *(float2*)(base  + nt * 8) = make_float2(oacc[nt][0] * inv0, oacc[nt][1] * inv0);
        *(float2*)(base8 + nt * 8) = make_float2(oacc[nt][2] * inv1, oacc[nt][3] * inv1);
    }
}

// ---------------------------------------------------------------------------
// Launch
// ---------------------------------------------------------------------------
extern "C" void kernel_launch(void* const* d_in, const int* in_sizes, int n_in,
                              void* d_out, int out_size)
{
    const float* x  = (const float*)d_in[0];
    const float* Wq = (const float*)d_in[1];
    const float* bq = (const float*)d_in[2];
    const float* Wk = (const float*)d_in[3];
    const float* bk = (const float*)d_in[4];
    const float* Wv = (const float*)d_in[5];
    const float* bv = (const float*)d_in[6];
    const float* Wo = (const float*)d_in[7];
    const float* bo = (const float*)d_in[8];
    float* out = (float*)d_out;

    float *pQ, *pK, *pV, *pCTX;
    cudaGetSymbolAddress((void**)&pQ,   g_Q);
    cudaGetSymbolAddress((void**)&pK,   g_K);
    cudaGetSymbolAddress((void**)&pV,   g_V);
    cudaGetSymbolAddress((void**)&pCTX, g_CTX);

    dim3 qkv_grid(DMODEL / 128, MROWS / 128, 3);   // (8, 32, 3)
    gemm_qkv<<<qkv_grid, 256>>>(x, Wq, bq, Wk, bk, Wv, bv, pQ, pK, pV);

    dim3 attn_grid(SEQ / 64, BATCH * NHEAD);       // (32, 32)
    flash_h16<<<attn_grid, 128>>>(pQ, pK, pV, pCTX);

    dim3 out_grid(DMODEL / 128, MROWS / 128);      // (8, 32)
    gemm_out<<<out_grid, 256>>>(pCTX, Wo, bo, out);
}